// round 5
// baseline (speedup 1.0000x reference)
#include <cuda_runtime.h>
#include <math.h>

#define NB 64
#define NW 64
#define NS 1024
#define NCH (NB*NW)

// ---------------- scratch (static device globals; no allocation) ----------------
__device__ float g_V  [NCH*NS];     // current activation (B, W, S)
__device__ float g_PW [NCH*NS];     // pointwise-conv result
__device__ float g_HI [NCH*1078];   // high-pass coeffs levels 1..7 per channel
__device__ float g_LO8[NCH*14];     // coarsest lo
__device__ float g_HI8[NCH*14];     // coarsest hi

// ---------------- wavelet filter constants (FFMA-imm friendly literals) --------
#define RL0  0.11154074335008017f
#define RL1  0.4946238903983854f
#define RL2  0.7511339080215775f
#define RL3  0.3152503517092432f
#define RL4  (-0.22626469396516913f)
#define RL5  (-0.12976686756709563f)
#define RL6  0.09750160558707936f
#define RL7  0.02752286553001629f
#define RL8  (-0.031582039318031156f)
#define RL9  0.0005538422009938016f
#define RL10 0.004777257511010651f
#define RL11 (-0.00107730108499558f)
// RH[j] = (-1)^j * RL[11-j]  (this is both the analysis-hi filter and REC_HI)
#define RH0  (-0.00107730108499558f)
#define RH1  (-0.004777257511010651f)
#define RH2  0.0005538422009938016f
#define RH3  0.031582039318031156f
#define RH4  0.02752286553001629f
#define RH5  (-0.09750160558707936f)
#define RH6  (-0.12976686756709563f)
#define RH7  0.22626469396516913f
#define RH8  0.3152503517092432f
#define RH9  (-0.7511339080215775f)
#define RH10 0.4946238903983854f
#define RH11 (-0.11154074335008017f)

__device__ __forceinline__ float geluf(float x) {
    return 0.5f * x * (1.0f + erff(x * 0.7071067811865476f));
}

// ---------------- fc0: v[b,c,s] = x[b,s]*w0[0,c] + grid[s]*w0[1,c] + b0[c] -----
__global__ void __launch_bounds__(256) k_fc0(const float* __restrict__ x,
                                             const float* __restrict__ w0,
                                             const float* __restrict__ b0) {
    const int ch = blockIdx.x, b = ch >> 6, c = ch & 63;
    const float wa = w0[c], wb = w0[64 + c], bc = b0[c];
    const float* xb = x + (size_t)b * NS;
    float* vp = g_V + (size_t)ch * NS;
    for (int s = threadIdx.x; s < NS; s += 256)
        vp[s] = xb[s] * wa + (float)s * (1.0f / 1023.0f) * wb + bc;
}

// ---------------- analysis: 8-level DWT cascade, one block per (b,c) ----------
__global__ void __launch_bounds__(256) k_analysis() {
    const int ch = blockIdx.x;
    __shared__ float sA[1024];
    __shared__ float sB[520];
    const float* __restrict__ vp = g_V + (size_t)ch * NS;
    for (int i = threadIdx.x; i < NS; i += 256) sA[i] = vp[i];
    __syncthreads();

    float* cur = sA; float* nxt = sB;
    int N = NS;
    const int offs[7] = {0, 517, 781, 918, 992, 1034, 1060};
#pragma unroll
    for (int l = 0; l < 8; l++) {
        const int out = (N + 11) >> 1;
        for (int n = threadIdx.x; n < out; n += 256) {
            const int base = 2 * n - 10;
            float lo, hi;
            if (base >= 0 && base + 11 < N) {
                const float* xp = cur + base;
                float x0=xp[0],x1=xp[1],x2=xp[2],x3=xp[3],x4=xp[4],x5=xp[5];
                float x6=xp[6],x7=xp[7],x8=xp[8],x9=xp[9],x10=xp[10],x11=xp[11];
                lo = x0*RL0+x1*RL1+x2*RL2+x3*RL3+x4*RL4+x5*RL5
                   + x6*RL6+x7*RL7+x8*RL8+x9*RL9+x10*RL10+x11*RL11;
                hi = x0*RH0+x1*RH1+x2*RH2+x3*RH3+x4*RH4+x5*RH5
                   + x6*RH6+x7*RH7+x8*RH8+x9*RH9+x10*RH10+x11*RH11;
            } else {
                const float RLa[12]={RL0,RL1,RL2,RL3,RL4,RL5,RL6,RL7,RL8,RL9,RL10,RL11};
                const float RHa[12]={RH0,RH1,RH2,RH3,RH4,RH5,RH6,RH7,RH8,RH9,RH10,RH11};
                lo = 0.f; hi = 0.f;
#pragma unroll
                for (int k = 0; k < 12; k++) {
                    int i = base + k;
                    i = (i < 0) ? (-1 - i) : i;          // symmetric left reflect
                    i = (i >= N) ? (2 * N - 1 - i) : i;  // symmetric right reflect
                    float xv = cur[i];
                    lo += RLa[k] * xv;
                    hi += RHa[k] * xv;
                }
            }
            if (l < 7) {
                g_HI[(size_t)ch * 1078 + offs[l] + n] = hi;
                nxt[n] = lo;
            } else {
                g_LO8[ch * 14 + n] = lo;
                g_HI8[ch * 14 + n] = hi;
            }
        }
        __syncthreads();
        float* t = cur; cur = nxt; nxt = t;
        N = out;
    }
}

// ---------------- pointwise conv: PW[b,o,s] = sum_c V[b,c,s]*cw[o,c] + cb[o] --
__global__ void __launch_bounds__(256) k_pointwise(const float* __restrict__ cw,
                                                   const float* __restrict__ cb) {
    const int b = blockIdx.y;
    const int s0 = blockIdx.x * 64;
    __shared__ float sW [64 * 64];   // [o][c]
    __shared__ float sVt[64 * 68];   // [s][c] padded
    for (int i = threadIdx.x; i < 4096; i += 256) sW[i] = cw[i];
    for (int i = threadIdx.x; i < 4096; i += 256) {
        int c = i >> 6, sj = i & 63;
        sVt[sj * 68 + c] = g_V[(size_t)(b * 64 + c) * NS + s0 + sj];
    }
    __syncthreads();
    const int lane = threadIdx.x & 31, og = threadIdx.x >> 5;
    float acc0[8] = {0,0,0,0,0,0,0,0};
    float acc1[8] = {0,0,0,0,0,0,0,0};
    const float4* v0 = (const float4*)(sVt + lane * 68);
    const float4* v1 = (const float4*)(sVt + (lane + 32) * 68);
#pragma unroll
    for (int c4 = 0; c4 < 16; c4++) {
        float4 a = v0[c4], bb = v1[c4];
#pragma unroll
        for (int k = 0; k < 8; k++) {
            float4 w = *(const float4*)(sW + (og * 8 + k) * 64 + c4 * 4);
            acc0[k] += a.x*w.x + a.y*w.y + a.z*w.z + a.w*w.w;
            acc1[k] += bb.x*w.x + bb.y*w.y + bb.z*w.z + bb.w*w.w;
        }
    }
#pragma unroll
    for (int k = 0; k < 8; k++) {
        int o = og * 8 + k;
        float bias = cb[o];
        float* p = g_PW + (size_t)(b * 64 + o) * NS + s0;
        p[lane]      = acc0[k] + bias;
        p[lane + 32] = acc1[k] + bias;
    }
}

// ---------------- one synthesis level (pair trick: no bounds checks needed) ---
__device__ __forceinline__ void sfb_pair(const float* __restrict__ lo,
                                         const float* __restrict__ hi,
                                         float* __restrict__ outb, int N) {
    const int half = N - 5;  // outLen/2 = (2N-10)/2
    for (int q = threadIdx.x; q < half; q += 256) {
        int u = q + 5;
        float l = lo[u], h = hi[u];
        float aE = l*RL0  + h*RH0;
        float aO = l*RL1  + h*RH1;
        u--; l = lo[u]; h = hi[u];
        aE += l*RL2  + h*RH2;  aO += l*RL3  + h*RH3;
        u--; l = lo[u]; h = hi[u];
        aE += l*RL4  + h*RH4;  aO += l*RL5  + h*RH5;
        u--; l = lo[u]; h = hi[u];
        aE += l*RL6  + h*RH6;  aO += l*RL7  + h*RH7;
        u--; l = lo[u]; h = hi[u];
        aE += l*RL8  + h*RH8;  aO += l*RL9  + h*RH9;
        u--; l = lo[u]; h = hi[u];
        aE += l*RL10 + h*RH10; aO += l*RL11 + h*RH11;
        outb[2 * q]     = aE;
        outb[2 * q + 1] = aO;
    }
}

// ---------------- synthesis: mix (fused) + 8-level IDWT + add PW + gelu -------
__global__ void __launch_bounds__(256) k_synth(const float* __restrict__ w1,
                                               const float* __restrict__ w2,
                                               int do_gelu) {
    const int o = blockIdx.x, b = blockIdx.y;
    __shared__ float sA[518];
    __shared__ float sB[1024];
    __shared__ float sLoRaw[896], sHiRaw[896];
    __shared__ float sLo[14], sHi[14];
    for (int i = threadIdx.x; i < 896; i += 256) {
        sLoRaw[i] = g_LO8[b * 896 + i];
        sHiRaw[i] = g_HI8[b * 896 + i];
    }
    __syncthreads();
    // coarse-level channel mix: out[o,x] = sum_i raw[i,x] * w[(i*64+o)*14+x]
    if (threadIdx.x < 28) {
        int x = threadIdx.x % 14, which = threadIdx.x / 14;
        const float* wm  = which ? w2 : w1;
        const float* src = which ? sHiRaw : sLoRaw;
        float acc = 0.f;
#pragma unroll 4
        for (int i = 0; i < 64; i++)
            acc += src[i * 14 + x] * wm[(i * 64 + o) * 14 + x];
        if (which) sHi[x] = acc; else sLo[x] = acc;
    }
    __syncthreads();

    // cascade: 14 ->18 ->26 ->42 ->74 ->138(137) ->264 ->518(517) ->1024
    sfb_pair(sLo, sHi, sA, 14);
    __syncthreads();
    const float* hibase = g_HI + (size_t)(b * 64 + o) * 1078;
    const int hN  [7] = {18, 26, 42, 74, 137, 264, 517};
    const int hOff[7] = {1060, 1034, 992, 918, 781, 517, 0};
    const float* cur = sA;
#pragma unroll
    for (int j = 0; j < 7; j++) {
        float* outb = ((j & 1) == 0) ? sB : sA;
        sfb_pair(cur, hibase + hOff[j], outb, hN[j]);
        __syncthreads();
        cur = outb;
    }
    // cur == sB, length 1024
    const float* pw = g_PW + (size_t)(b * 64 + o) * NS;
    float* vout = g_V + (size_t)(b * 64 + o) * NS;
    if (do_gelu) {
        for (int s = threadIdx.x; s < NS; s += 256) vout[s] = geluf(sB[s] + pw[s]);
    } else {
        for (int s = threadIdx.x; s < NS; s += 256) vout[s] = sB[s] + pw[s];
    }
}

// ---------------- head: out[b,s] (+)= fc2(gelu(fc1(v[b,:,s]))) ----------------
__global__ void __launch_bounds__(128) k_fc(const float* __restrict__ w1,
                                            const float* __restrict__ b1,
                                            const float* __restrict__ w2,
                                            const float* __restrict__ b2,
                                            float* __restrict__ out, int add) {
    const int b = blockIdx.y, s0 = blockIdx.x * 128, t = threadIdx.x;
    __shared__ float sW1[128 * 68];   // [h][c] padded
    __shared__ float sB1[128], sW2[128];
    for (int i = t; i < 8192; i += 128) {
        int c = i >> 7, h = i & 127;
        sW1[h * 68 + c] = w1[i];      // w1 is [c][h] row-major
    }
    sB1[t] = b1[t];
    sW2[t] = w2[t];
    float4 vr4[16];
    {
        float* vf = (float*)vr4;
        const float* vbase = g_V + (size_t)b * NW * NS + s0 + t;
#pragma unroll
        for (int c = 0; c < 64; c++) vf[c] = vbase[(size_t)c * NS];
    }
    __syncthreads();
    float res = 0.f;
#pragma unroll 2
    for (int h = 0; h < 128; h++) {
        const float4* wr = (const float4*)(sW1 + h * 68);
        float a0 = 0, a1 = 0, a2 = 0, a3 = 0;
#pragma unroll
        for (int c4 = 0; c4 < 16; c4++) {
            float4 w = wr[c4]; float4 v = vr4[c4];
            a0 += v.x * w.x; a1 += v.y * w.y; a2 += v.z * w.z; a3 += v.w * w.w;
        }
        float hv = (a0 + a2) + (a1 + a3) + sB1[h];
        res += geluf(hv) * sW2[h];
    }
    res += b2[0];
    int idx = b * NS + s0 + t;
    if (add) out[idx] += res; else out[idx] = res;
}

// ---------------- launch ------------------------------------------------------
extern "C" void kernel_launch(void* const* d_in, const int* in_sizes, int n_in,
                              void* d_out, int out_size) {
    (void)in_sizes; (void)n_in; (void)out_size;
    const float* x = (const float*)d_in[0];
    float* out = (float*)d_out;
    for (int br = 0; br < 2; br++) {
        const int base = 1 + br * 10;
        const float* fc0_w = (const float*)d_in[base + 0];
        const float* fc0_b = (const float*)d_in[base + 1];
        const float* ww1   = (const float*)d_in[base + 2];
        const float* ww2   = (const float*)d_in[base + 3];
        const float* cw    = (const float*)d_in[base + 4];
        const float* cb    = (const float*)d_in[base + 5];
        const float* f1w   = (const float*)d_in[base + 6];
        const float* f1b   = (const float*)d_in[base + 7];
        const float* f2w   = (const float*)d_in[base + 8];
        const float* f2b   = (const float*)d_in[base + 9];

        k_fc0<<<NCH, 256>>>(x, fc0_w, fc0_b);
        for (int l = 0; l < 4; l++) {
            k_analysis<<<NCH, 256>>>();
            k_pointwise<<<dim3(16, 64), 256>>>(cw + l * 4096, cb + l * 64);
            k_synth<<<dim3(64, 64), 256>>>(ww1 + l * 57344, ww2 + l * 57344,
                                           (l < 3) ? 1 : 0);
        }
        k_fc<<<dim3(8, 64), 128>>>(f1w, f1b, f2w, f2b, out, br);
    }
}